// round 1
// baseline (speedup 1.0000x reference)
#include <cuda_runtime.h>
#include <math.h>

#define BATCH 4
#define RAYS  8192
#define NRAYS (BATCH*RAYS)          // 32768
#define NS    48
#define RES   48
#define CH    32
#define NPTS  (NRAYS*NS)            // 1572864

#define DT    0.03125f              // (FAR-NEAR)/NS = 1.5/48

// ---------------- device scratch (no runtime allocation allowed) ----------------
__device__ __align__(16) float g_mat_t[3*BATCH*RES*RES*CH];  // channel-last planes
__device__ __align__(16) float g_vec_t[3*BATCH*RES*CH];      // channel-last lines
__device__ __align__(16) float g_rgb[(size_t)NPTS*3];        // per-point rgb
__device__ __align__(16) float g_pe[NRAYS*27];               // per-ray PE(viewdir)

__device__ __forceinline__ float gelu_exact(float x) {
    // jax.nn.gelu(approximate=False) = x * Phi(x)
    return x * normcdff(x);
}

// ---------------- prep: transpose matrixs (3,B,C,48,48) -> (3,B,48,48,C) --------
__global__ void k_transpose_mat(const float* __restrict__ m) {
    int idx = blockIdx.x * blockDim.x + threadIdx.x;
    if (idx >= 3*BATCH*RES*RES*CH) return;
    int c   = idx % CH;
    int pix = (idx / CH) % (RES*RES);
    int ib  = idx / (CH*RES*RES);
    g_mat_t[idx] = m[((size_t)ib*CH + c)*(RES*RES) + pix];
}

// ---------------- prep: transpose vectors (3,B,C,48) -> (3,B,48,C) --------------
__global__ void k_transpose_vec(const float* __restrict__ v) {
    int idx = blockIdx.x * blockDim.x + threadIdx.x;
    if (idx >= 3*BATCH*RES*CH) return;
    int c  = idx % CH;
    int r  = (idx / CH) % RES;
    int ib = idx / (CH*RES);
    g_vec_t[idx] = v[((size_t)ib*CH + c)*RES + r];
}

// ---------------- prep: positional encoding of normalized view dirs -------------
__global__ void k_pe(const float* __restrict__ rays_d) {
    int q = blockIdx.x * blockDim.x + threadIdx.x;
    if (q >= NRAYS) return;
    float dx = rays_d[q*3+0], dy = rays_d[q*3+1], dz = rays_d[q*3+2];
    float inv = 1.0f / sqrtf(dx*dx + dy*dy + dz*dz);
    dx *= inv; dy *= inv; dz *= inv;
    float* o = g_pe + q*27;
    o[0] = dx; o[1] = dy; o[2] = dz;
    float f = 1.0f;
    #pragma unroll
    for (int fi = 0; fi < 4; fi++) {
        float s, c;
        sincosf(dx*f, &s, &c); o[3 + fi*3 + 0] = s; o[15 + fi*3 + 0] = c;
        sincosf(dy*f, &s, &c); o[3 + fi*3 + 1] = s; o[15 + fi*3 + 1] = c;
        sincosf(dz*f, &s, &c); o[3 + fi*3 + 2] = s; o[15 + fi*3 + 2] = c;
        f *= 2.0f;
    }
}

// ---------------- main per-point kernel: sample features + MLP ------------------
__global__ __launch_bounds__(128)
void k_points(const float* __restrict__ rays_o, const float* __restrict__ rays_d,
              const float* __restrict__ w_mat, const float* __restrict__ b_mat,
              const float* __restrict__ w1,    const float* __restrict__ b1,
              const float* __restrict__ w2,    const float* __restrict__ b2,
              float* __restrict__ out_sigma) {
    __shared__ __align__(16) float s_wmat[72*64];   // [k][j], j contiguous
    __shared__ __align__(16) float s_w1t[64*96];    // transposed: [j][k], k padded to 96
    __shared__ float s_w2[64*3];
    __shared__ float s_bmat[64];
    __shared__ float s_b1[64];
    __shared__ float s_b2[3];

    const int tid = threadIdx.x;
    for (int i = tid; i < 72*64; i += 128) s_wmat[i] = w_mat[i];
    for (int i = tid; i < 64*96; i += 128) {
        int j = i / 96, k = i % 96;
        s_w1t[i] = (k < 91) ? w1[k*64 + j] : 0.0f;
    }
    for (int i = tid; i < 192; i += 128) s_w2[i] = w2[i];
    if (tid < 64) { s_bmat[tid] = b_mat[tid]; s_b1[tid] = b1[tid]; }
    if (tid < 3)  s_b2[tid] = b2[tid];
    __syncthreads();

    const int p   = blockIdx.x * 128 + tid;
    const int s   = p % NS;
    const int ray = p / NS;
    const int b   = ray / RAYS;

    const float ox = rays_o[ray*3+0], oy = rays_o[ray*3+1], oz = rays_o[ray*3+2];
    const float dx = rays_d[ray*3+0], dy = rays_d[ray*3+1], dz = rays_d[ray*3+2];
    const float t  = ((float)s + 0.5f) * DT;

    // xyz in [-1,1] box coords
    const float px = ((ox + dx*t) + 0.8f) * 1.25f - 1.0f;
    const float py = ((oy + dy*t) + 0.8f) * 1.25f - 1.0f;
    const float pz = ((oz + dz*t) + 0.8f) * 1.25f - 1.0f;

    float h[64];
    #pragma unroll
    for (int j = 0; j < 64; j++) h[j] = s_bmat[j];
    float sigma = 0.0f;

    #pragma unroll 1
    for (int pl = 0; pl < 3; pl++) {
        // MAT_MODE = [[0,1],[2,0],[1,2]], VEC_MODE = [2,1,0]
        const float cx = (pl == 0) ? px : ((pl == 1) ? pz : py);
        const float cy = (pl == 0) ? py : ((pl == 1) ? px : pz);
        const float cz = (pl == 0) ? pz : ((pl == 1) ? py : px);

        const float fx = (cx + 1.0f) * 23.5f;
        const float fy = (cy + 1.0f) * 23.5f;
        const float fz = (cz + 1.0f) * 23.5f;
        const float x0f = floorf(fx), y0f = floorf(fy), z0f = floorf(fz);
        const float wx = fx - x0f, wy = fy - y0f, wz = fz - z0f;
        const int ix0 = (int)x0f, iy0 = (int)y0f, iz0 = (int)z0f;

        const float mx0 = (ix0 >= 0  && ix0 <  RES)   ? 1.0f : 0.0f;
        const float mx1 = (ix0 >= -1 && ix0 <  RES-1) ? 1.0f : 0.0f;
        const float my0 = (iy0 >= 0  && iy0 <  RES)   ? 1.0f : 0.0f;
        const float my1 = (iy0 >= -1 && iy0 <  RES-1) ? 1.0f : 0.0f;
        const float mz0 = (iz0 >= 0  && iz0 <  RES)   ? 1.0f : 0.0f;
        const float mz1 = (iz0 >= -1 && iz0 <  RES-1) ? 1.0f : 0.0f;

        const int cx0 = min(max(ix0,   0), RES-1), cx1 = min(max(ix0+1, 0), RES-1);
        const int cy0 = min(max(iy0,   0), RES-1), cy1 = min(max(iy0+1, 0), RES-1);
        const int cz0 = min(max(iz0,   0), RES-1), cz1 = min(max(iz0+1, 0), RES-1);

        const float w00 = (1.0f-wx)*(1.0f-wy)*mx0*my0;
        const float w10 = wx*(1.0f-wy)*mx1*my0;
        const float w01 = (1.0f-wx)*wy*mx0*my1;
        const float w11 = wx*wy*mx1*my1;
        const float u0  = (1.0f-wz)*mz0;
        const float u1  = wz*mz1;

        const float* mb = g_mat_t + ((size_t)(pl*BATCH + b) * (RES*RES)) * CH;
        const float* vb = g_vec_t + ((size_t)(pl*BATCH + b) * RES) * CH;
        const float4* p00 = (const float4*)(mb + (size_t)(cy0*RES + cx0) * CH);
        const float4* p10 = (const float4*)(mb + (size_t)(cy0*RES + cx1) * CH);
        const float4* p01 = (const float4*)(mb + (size_t)(cy1*RES + cx0) * CH);
        const float4* p11 = (const float4*)(mb + (size_t)(cy1*RES + cx1) * CH);
        const float4* q0  = (const float4*)(vb + (size_t)cz0 * CH);
        const float4* q1  = (const float4*)(vb + (size_t)cz1 * CH);

        // channels 0..7 -> sigma
        #pragma unroll 1
        for (int ch = 0; ch < 2; ch++) {
            float4 a = p00[ch], bb = p10[ch], c4 = p01[ch], d4 = p11[ch];
            float4 e = q0[ch],  f4 = q1[ch];
            float pf0 = w00*a.x + w10*bb.x + w01*c4.x + w11*d4.x;
            float pf1 = w00*a.y + w10*bb.y + w01*c4.y + w11*d4.y;
            float pf2 = w00*a.z + w10*bb.z + w01*c4.z + w11*d4.z;
            float pf3 = w00*a.w + w10*bb.w + w01*c4.w + w11*d4.w;
            float lf0 = u0*e.x + u1*f4.x;
            float lf1 = u0*e.y + u1*f4.y;
            float lf2 = u0*e.z + u1*f4.z;
            float lf3 = u0*e.w + u1*f4.w;
            sigma += pf0*lf0 + pf1*lf1 + pf2*lf2 + pf3*lf3;
        }
        // channels 8..31 -> gelu -> layer-1 accumulate (features never materialized)
        #pragma unroll 1
        for (int ch = 2; ch < 8; ch++) {
            float4 a = p00[ch], bb = p10[ch], c4 = p01[ch], d4 = p11[ch];
            float4 e = q0[ch],  f4 = q1[ch];
            float g0 = gelu_exact((w00*a.x + w10*bb.x + w01*c4.x + w11*d4.x) * (u0*e.x + u1*f4.x));
            float g1 = gelu_exact((w00*a.y + w10*bb.y + w01*c4.y + w11*d4.y) * (u0*e.y + u1*f4.y));
            float g2 = gelu_exact((w00*a.z + w10*bb.z + w01*c4.z + w11*d4.z) * (u0*e.z + u1*f4.z));
            float g3 = gelu_exact((w00*a.w + w10*bb.w + w01*c4.w + w11*d4.w) * (u0*e.w + u1*f4.w));
            const int kb = pl*24 + (ch-2)*4;
            const float* wr0 = s_wmat + (kb+0)*64;
            const float* wr1 = s_wmat + (kb+1)*64;
            const float* wr2 = s_wmat + (kb+2)*64;
            const float* wr3 = s_wmat + (kb+3)*64;
            #pragma unroll
            for (int j = 0; j < 64; j += 4) {
                float4 a0 = *(const float4*)(wr0 + j);
                float4 a1 = *(const float4*)(wr1 + j);
                float4 a2 = *(const float4*)(wr2 + j);
                float4 a3 = *(const float4*)(wr3 + j);
                h[j+0] += g0*a0.x + g1*a1.x + g2*a2.x + g3*a3.x;
                h[j+1] += g0*a0.y + g1*a1.y + g2*a2.y + g3*a3.y;
                h[j+2] += g0*a0.z + g1*a1.z + g2*a2.z + g3*a3.z;
                h[j+3] += g0*a0.w + g1*a1.w + g2*a2.w + g3*a3.w;
            }
        }
    }

    out_sigma[p] = fmaxf(sigma, 0.0f);

    // layer 2 input: [gelu(h) (64), pe (27), pad (1)]
    float in[92];
    #pragma unroll
    for (int j = 0; j < 64; j++) in[j] = gelu_exact(h[j]);
    const float* pe = g_pe + ray*27;
    #pragma unroll
    for (int k = 0; k < 27; k++) in[64+k] = pe[k];
    in[91] = 0.0f;

    float r0 = s_b2[0], r1 = s_b2[1], r2 = s_b2[2];
    #pragma unroll 1
    for (int j = 0; j < 64; j++) {
        const float4* wr = (const float4*)(s_w1t + j*96);
        float acc = s_b1[j];
        #pragma unroll
        for (int c = 0; c < 23; c++) {
            float4 w = wr[c];
            acc += in[c*4+0]*w.x + in[c*4+1]*w.y + in[c*4+2]*w.z + in[c*4+3]*w.w;
        }
        float g = gelu_exact(acc);
        r0 += g * s_w2[j*3+0];
        r1 += g * s_w2[j*3+1];
        r2 += g * s_w2[j*3+2];
    }

    float* ro = g_rgb + (size_t)p*3;
    ro[0] = 1.0f / (1.0f + expf(-r0));
    ro[1] = 1.0f / (1.0f + expf(-r1));
    ro[2] = 1.0f / (1.0f + expf(-r2));
}

// ---------------- per-ray compositing (sigma in-place -> weights) ---------------
__global__ void k_render(float* __restrict__ out_rgb, float* __restrict__ out_depth,
                         float* __restrict__ w) {
    int q = blockIdx.x * blockDim.x + threadIdx.x;
    if (q >= NRAYS) return;
    float T = 1.0f, a0 = 0.0f, a1 = 0.0f, a2 = 0.0f, dep = 0.0f;
    const float* rp = g_rgb + (size_t)q * NS * 3;
    float* wp = w + (size_t)q * NS;
    #pragma unroll 1
    for (int s = 0; s < NS; s++) {
        float sg = wp[s];
        float al = 1.0f - expf(-sg * DT);
        float wt = al * T;
        T *= (1.0f - al + 1e-10f);
        wp[s] = wt;
        dep += wt * (((float)s + 0.5f) * DT);
        a0 += wt * rp[s*3+0];
        a1 += wt * rp[s*3+1];
        a2 += wt * rp[s*3+2];
    }
    out_rgb[q*3+0] = a0;
    out_rgb[q*3+1] = a1;
    out_rgb[q*3+2] = a2;
    out_depth[q]   = dep;
}

// ---------------- launch --------------------------------------------------------
extern "C" void kernel_launch(void* const* d_in, const int* in_sizes, int n_in,
                              void* d_out, int out_size) {
    const float* rays_o  = (const float*)d_in[0];
    const float* rays_d  = (const float*)d_in[1];
    const float* matrixs = (const float*)d_in[2];
    const float* vectors = (const float*)d_in[3];
    const float* w_mat   = (const float*)d_in[4];
    const float* b_mat   = (const float*)d_in[5];
    const float* w1      = (const float*)d_in[6];
    const float* b1      = (const float*)d_in[7];
    const float* w2      = (const float*)d_in[8];
    const float* b2      = (const float*)d_in[9];

    float* out       = (float*)d_out;
    float* out_rgb   = out;                 // (B,R,3)
    float* out_depth = out + NRAYS*3;       // (B,R)
    float* out_w     = out + NRAYS*4;       // (B,R,NS)

    k_transpose_mat<<<(3*BATCH*RES*RES*CH + 255)/256, 256>>>(matrixs);
    k_transpose_vec<<<(3*BATCH*RES*CH + 255)/256, 256>>>(vectors);
    k_pe<<<(NRAYS + 255)/256, 256>>>(rays_d);
    k_points<<<NPTS/128, 128>>>(rays_o, rays_d, w_mat, b_mat, w1, b1, w2, b2, out_w);
    k_render<<<(NRAYS + 127)/128, 128>>>(out_rgb, out_depth, out_w);
}

// round 2
// speedup vs baseline: 1.1103x; 1.1103x over previous
#include <cuda_runtime.h>
#include <math.h>

#define BATCH 4
#define RAYS  8192
#define NRAYS (BATCH*RAYS)          // 32768
#define NS    48
#define RES   48
#define CH    32
#define NPTS  (NRAYS*NS)            // 1572864

#define DT    0.03125f              // (FAR-NEAR)/NS = 1.5/48

// ---------------- device scratch (no runtime allocation allowed) ----------------
__device__ __align__(16) float g_mat_t[3*BATCH*RES*RES*CH];  // channel-last planes
__device__ __align__(16) float g_vec_t[3*BATCH*RES*CH];      // channel-last lines
__device__ __align__(16) float g_rgb[(size_t)NPTS*3];        // per-point rgb
__device__ __align__(16) float g_pe[NRAYS*27];               // per-ray PE(viewdir)
__device__ __align__(16) float g_h[(size_t)64*NPTS];         // gelu(h) staged [j][p]

__device__ __forceinline__ float gelu_exact(float x) {
    // jax.nn.gelu(approximate=False) = 0.5*x*(1+erf(x/sqrt(2)))
    return 0.5f * x * (1.0f + erff(x * 0.70710678118654752f));
}

// ---------------- prep: transpose matrixs (3,B,C,48,48) -> (3,B,48,48,C) --------
__global__ void k_transpose_mat(const float* __restrict__ m) {
    int idx = blockIdx.x * blockDim.x + threadIdx.x;
    if (idx >= 3*BATCH*RES*RES*CH) return;
    int c   = idx % CH;
    int pix = (idx / CH) % (RES*RES);
    int ib  = idx / (CH*RES*RES);
    g_mat_t[idx] = m[((size_t)ib*CH + c)*(RES*RES) + pix];
}

// ---------------- prep: transpose vectors (3,B,C,48) -> (3,B,48,C) --------------
__global__ void k_transpose_vec(const float* __restrict__ v) {
    int idx = blockIdx.x * blockDim.x + threadIdx.x;
    if (idx >= 3*BATCH*RES*CH) return;
    int c  = idx % CH;
    int r  = (idx / CH) % RES;
    int ib = idx / (CH*RES);
    g_vec_t[idx] = v[((size_t)ib*CH + c)*RES + r];
}

// ---------------- prep: positional encoding of normalized view dirs -------------
__global__ void k_pe(const float* __restrict__ rays_d) {
    int q = blockIdx.x * blockDim.x + threadIdx.x;
    if (q >= NRAYS) return;
    float dx = rays_d[q*3+0], dy = rays_d[q*3+1], dz = rays_d[q*3+2];
    float inv = 1.0f / sqrtf(dx*dx + dy*dy + dz*dz);
    dx *= inv; dy *= inv; dz *= inv;
    float* o = g_pe + q*27;
    o[0] = dx; o[1] = dy; o[2] = dz;
    float f = 1.0f;
    #pragma unroll
    for (int fi = 0; fi < 4; fi++) {
        float s, c;
        sincosf(dx*f, &s, &c); o[3 + fi*3 + 0] = s; o[15 + fi*3 + 0] = c;
        sincosf(dy*f, &s, &c); o[3 + fi*3 + 1] = s; o[15 + fi*3 + 1] = c;
        sincosf(dz*f, &s, &c); o[3 + fi*3 + 2] = s; o[15 + fi*3 + 2] = c;
        f *= 2.0f;
    }
}

// ---------------- kernel A: sample features + layer "mat" + gelu ----------------
__global__ __launch_bounds__(128, 3)
void k_pointsA(const float* __restrict__ rays_o, const float* __restrict__ rays_d,
               const float* __restrict__ w_mat, const float* __restrict__ b_mat,
               float* __restrict__ out_sigma) {
    __shared__ __align__(16) float s_wmat[72*64];   // [k][j], j contiguous
    __shared__ float s_bmat[64];

    const int tid = threadIdx.x;
    for (int i = tid; i < 72*64; i += 128) s_wmat[i] = w_mat[i];
    if (tid < 64) s_bmat[tid] = b_mat[tid];
    __syncthreads();

    const int p   = blockIdx.x * 128 + tid;
    const int s   = p % NS;
    const int ray = p / NS;
    const int b   = ray / RAYS;

    const float ox = rays_o[ray*3+0], oy = rays_o[ray*3+1], oz = rays_o[ray*3+2];
    const float dx = rays_d[ray*3+0], dy = rays_d[ray*3+1], dz = rays_d[ray*3+2];
    const float t  = ((float)s + 0.5f) * DT;

    const float px = ((ox + dx*t) + 0.8f) * 1.25f - 1.0f;
    const float py = ((oy + dy*t) + 0.8f) * 1.25f - 1.0f;
    const float pz = ((oz + dz*t) + 0.8f) * 1.25f - 1.0f;

    float h[64];
    #pragma unroll
    for (int j = 0; j < 64; j++) h[j] = s_bmat[j];
    float sigma = 0.0f;

    #pragma unroll 1
    for (int pl = 0; pl < 3; pl++) {
        // MAT_MODE = [[0,1],[2,0],[1,2]], VEC_MODE = [2,1,0]
        const float cx = (pl == 0) ? px : ((pl == 1) ? pz : py);
        const float cy = (pl == 0) ? py : ((pl == 1) ? px : pz);
        const float cz = (pl == 0) ? pz : ((pl == 1) ? py : px);

        const float fx = (cx + 1.0f) * 23.5f;
        const float fy = (cy + 1.0f) * 23.5f;
        const float fz = (cz + 1.0f) * 23.5f;
        const float x0f = floorf(fx), y0f = floorf(fy), z0f = floorf(fz);
        const float wx = fx - x0f, wy = fy - y0f, wz = fz - z0f;
        const int ix0 = (int)x0f, iy0 = (int)y0f, iz0 = (int)z0f;

        const float mx0 = (ix0 >= 0  && ix0 <  RES)   ? 1.0f : 0.0f;
        const float mx1 = (ix0 >= -1 && ix0 <  RES-1) ? 1.0f : 0.0f;
        const float my0 = (iy0 >= 0  && iy0 <  RES)   ? 1.0f : 0.0f;
        const float my1 = (iy0 >= -1 && iy0 <  RES-1) ? 1.0f : 0.0f;
        const float mz0 = (iz0 >= 0  && iz0 <  RES)   ? 1.0f : 0.0f;
        const float mz1 = (iz0 >= -1 && iz0 <  RES-1) ? 1.0f : 0.0f;

        const int cx0 = min(max(ix0,   0), RES-1), cx1 = min(max(ix0+1, 0), RES-1);
        const int cy0 = min(max(iy0,   0), RES-1), cy1 = min(max(iy0+1, 0), RES-1);
        const int cz0 = min(max(iz0,   0), RES-1), cz1 = min(max(iz0+1, 0), RES-1);

        const float w00 = (1.0f-wx)*(1.0f-wy)*mx0*my0;
        const float w10 = wx*(1.0f-wy)*mx1*my0;
        const float w01 = (1.0f-wx)*wy*mx0*my1;
        const float w11 = wx*wy*mx1*my1;
        const float u0  = (1.0f-wz)*mz0;
        const float u1  = wz*mz1;

        const float* mb = g_mat_t + ((size_t)(pl*BATCH + b) * (RES*RES)) * CH;
        const float* vb = g_vec_t + ((size_t)(pl*BATCH + b) * RES) * CH;
        const float4* p00 = (const float4*)(mb + (size_t)(cy0*RES + cx0) * CH);
        const float4* p10 = (const float4*)(mb + (size_t)(cy0*RES + cx1) * CH);
        const float4* p01 = (const float4*)(mb + (size_t)(cy1*RES + cx0) * CH);
        const float4* p11 = (const float4*)(mb + (size_t)(cy1*RES + cx1) * CH);
        const float4* q0  = (const float4*)(vb + (size_t)cz0 * CH);
        const float4* q1  = (const float4*)(vb + (size_t)cz1 * CH);

        // channels 0..7 -> sigma
        #pragma unroll 1
        for (int ch = 0; ch < 2; ch++) {
            float4 a = p00[ch], bb = p10[ch], c4 = p01[ch], d4 = p11[ch];
            float4 e = q0[ch],  f4 = q1[ch];
            float pf0 = w00*a.x + w10*bb.x + w01*c4.x + w11*d4.x;
            float pf1 = w00*a.y + w10*bb.y + w01*c4.y + w11*d4.y;
            float pf2 = w00*a.z + w10*bb.z + w01*c4.z + w11*d4.z;
            float pf3 = w00*a.w + w10*bb.w + w01*c4.w + w11*d4.w;
            float lf0 = u0*e.x + u1*f4.x;
            float lf1 = u0*e.y + u1*f4.y;
            float lf2 = u0*e.z + u1*f4.z;
            float lf3 = u0*e.w + u1*f4.w;
            sigma += pf0*lf0 + pf1*lf1 + pf2*lf2 + pf3*lf3;
        }
        // channels 8..31 -> gelu -> layer-1 accumulate
        #pragma unroll 1
        for (int ch = 2; ch < 8; ch++) {
            float4 a = p00[ch], bb = p10[ch], c4 = p01[ch], d4 = p11[ch];
            float4 e = q0[ch],  f4 = q1[ch];
            float g0 = gelu_exact((w00*a.x + w10*bb.x + w01*c4.x + w11*d4.x) * (u0*e.x + u1*f4.x));
            float g1 = gelu_exact((w00*a.y + w10*bb.y + w01*c4.y + w11*d4.y) * (u0*e.y + u1*f4.y));
            float g2 = gelu_exact((w00*a.z + w10*bb.z + w01*c4.z + w11*d4.z) * (u0*e.z + u1*f4.z));
            float g3 = gelu_exact((w00*a.w + w10*bb.w + w01*c4.w + w11*d4.w) * (u0*e.w + u1*f4.w));
            const int kb = pl*24 + (ch-2)*4;
            const float* wr0 = s_wmat + (kb+0)*64;
            const float* wr1 = s_wmat + (kb+1)*64;
            const float* wr2 = s_wmat + (kb+2)*64;
            const float* wr3 = s_wmat + (kb+3)*64;
            #pragma unroll
            for (int j = 0; j < 64; j += 4) {
                float4 a0 = *(const float4*)(wr0 + j);
                float4 a1 = *(const float4*)(wr1 + j);
                float4 a2 = *(const float4*)(wr2 + j);
                float4 a3 = *(const float4*)(wr3 + j);
                h[j+0] += g0*a0.x + g1*a1.x + g2*a2.x + g3*a3.x;
                h[j+1] += g0*a0.y + g1*a1.y + g2*a2.y + g3*a3.y;
                h[j+2] += g0*a0.z + g1*a1.z + g2*a2.z + g3*a3.z;
                h[j+3] += g0*a0.w + g1*a1.w + g2*a2.w + g3*a3.w;
            }
        }
    }

    out_sigma[p] = fmaxf(sigma, 0.0f);

    // gelu + stage to global, layout [j][p] for coalesced streaming in kernel B
    #pragma unroll
    for (int j = 0; j < 64; j++) {
        g_h[(size_t)j*NPTS + p] = gelu_exact(h[j]);
    }
}

// ---------------- kernel B: layer1 (91->64) + layer2 (64->3) --------------------
__global__ __launch_bounds__(128, 4)
void k_pointsB(const float* __restrict__ w1, const float* __restrict__ b1,
               const float* __restrict__ w2, const float* __restrict__ b2) {
    __shared__ __align__(16) float s_w1[91*64];   // [k][j], j contiguous (native layout)
    __shared__ float s_w2[64*3];
    __shared__ float s_b1[64];
    __shared__ float s_b2[3];

    const int tid = threadIdx.x;
    for (int i = tid; i < 91*64; i += 128) s_w1[i] = w1[i];
    for (int i = tid; i < 192; i += 128) s_w2[i] = w2[i];
    if (tid < 64) s_b1[tid] = b1[tid];
    if (tid < 3)  s_b2[tid] = b2[tid];
    __syncthreads();

    const int p   = blockIdx.x * 128 + tid;
    const int ray = p / NS;

    float acc[64];
    #pragma unroll
    for (int j = 0; j < 64; j++) acc[j] = s_b1[j];

    // k-outer over the 64 staged activations (coalesced LDG per k)
    #pragma unroll 2
    for (int k = 0; k < 64; k++) {
        const float v = g_h[(size_t)k*NPTS + p];
        const float4* wr = (const float4*)(s_w1 + k*64);
        #pragma unroll
        for (int j = 0; j < 16; j++) {
            float4 w = wr[j];
            acc[j*4+0] += v*w.x;
            acc[j*4+1] += v*w.y;
            acc[j*4+2] += v*w.z;
            acc[j*4+3] += v*w.w;
        }
    }
    // k-outer over the 27 PE components (ray-uniform-ish, L1 resident)
    const float* pe = g_pe + ray*27;
    #pragma unroll 1
    for (int k = 0; k < 27; k++) {
        const float v = pe[k];
        const float4* wr = (const float4*)(s_w1 + (64+k)*64);
        #pragma unroll
        for (int j = 0; j < 16; j++) {
            float4 w = wr[j];
            acc[j*4+0] += v*w.x;
            acc[j*4+1] += v*w.y;
            acc[j*4+2] += v*w.z;
            acc[j*4+3] += v*w.w;
        }
    }

    float r0 = s_b2[0], r1 = s_b2[1], r2 = s_b2[2];
    #pragma unroll
    for (int j = 0; j < 64; j++) {
        float g = gelu_exact(acc[j]);
        r0 += g * s_w2[j*3+0];
        r1 += g * s_w2[j*3+1];
        r2 += g * s_w2[j*3+2];
    }

    float* ro = g_rgb + (size_t)p*3;
    ro[0] = 1.0f / (1.0f + expf(-r0));
    ro[1] = 1.0f / (1.0f + expf(-r1));
    ro[2] = 1.0f / (1.0f + expf(-r2));
}

// ---------------- per-ray compositing (sigma in-place -> weights) ---------------
__global__ void k_render(float* __restrict__ out_rgb, float* __restrict__ out_depth,
                         float* __restrict__ w) {
    int q = blockIdx.x * blockDim.x + threadIdx.x;
    if (q >= NRAYS) return;
    float T = 1.0f, a0 = 0.0f, a1 = 0.0f, a2 = 0.0f, dep = 0.0f;
    const float* rp = g_rgb + (size_t)q * NS * 3;
    float* wp = w + (size_t)q * NS;
    #pragma unroll 1
    for (int s = 0; s < NS; s++) {
        float sg = wp[s];
        float al = 1.0f - expf(-sg * DT);
        float wt = al * T;
        T *= (1.0f - al + 1e-10f);
        wp[s] = wt;
        dep += wt * (((float)s + 0.5f) * DT);
        a0 += wt * rp[s*3+0];
        a1 += wt * rp[s*3+1];
        a2 += wt * rp[s*3+2];
    }
    out_rgb[q*3+0] = a0;
    out_rgb[q*3+1] = a1;
    out_rgb[q*3+2] = a2;
    out_depth[q]   = dep;
}

// ---------------- launch --------------------------------------------------------
extern "C" void kernel_launch(void* const* d_in, const int* in_sizes, int n_in,
                              void* d_out, int out_size) {
    const float* rays_o  = (const float*)d_in[0];
    const float* rays_d  = (const float*)d_in[1];
    const float* matrixs = (const float*)d_in[2];
    const float* vectors = (const float*)d_in[3];
    const float* w_mat   = (const float*)d_in[4];
    const float* b_mat   = (const float*)d_in[5];
    const float* w1      = (const float*)d_in[6];
    const float* b1      = (const float*)d_in[7];
    const float* w2      = (const float*)d_in[8];
    const float* b2      = (const float*)d_in[9];

    float* out       = (float*)d_out;
    float* out_rgb   = out;                 // (B,R,3)
    float* out_depth = out + NRAYS*3;       // (B,R)
    float* out_w     = out + NRAYS*4;       // (B,R,NS)

    k_transpose_mat<<<(3*BATCH*RES*RES*CH + 255)/256, 256>>>(matrixs);
    k_transpose_vec<<<(3*BATCH*RES*CH + 255)/256, 256>>>(vectors);
    k_pe<<<(NRAYS + 255)/256, 256>>>(rays_d);
    k_pointsA<<<NPTS/128, 128>>>(rays_o, rays_d, w_mat, b_mat, out_w);
    k_pointsB<<<NPTS/128, 128>>>(w1, b1, w2, b2);
    k_render<<<(NRAYS + 127)/128, 128>>>(out_rgb, out_depth, out_w);
}